// round 4
// baseline (speedup 1.0000x reference)
#include <cuda_runtime.h>

// Problem constants
#define NB 2048   // batch
#define NT 1024   // timesteps
#define ND 64     // input size
#define NH 32     // hidden
#define NG 96     // 3*H

#define WPB 7                 // warps per block
#define NBLK 148              // one block per SM, single wave
#define NTHREADS (WPB * 32)

// Shared memory layout (float offsets)
#define OFF_WIH0 0            // 96*64 = 6144
#define OFF_WHH0 6144         // 96*32 = 3072
#define OFF_WIH1 9216         // 3072
#define OFF_WHH1 12288        // 3072
#define OFF_BIAS 15360        // 8*32 = 256
#define OFF_X    15616        // 7 warps * 2 rows * 64 = 896
#define OFF_H0   16512        // 7*2*32 = 448
#define OFF_H1   16960        // 448
#define SMEM_FLOATS 17408     // 69632 bytes

__device__ __forceinline__ float sigm(float x) {
    return __fdividef(1.0f, 1.0f + __expf(-x));
}
__device__ __forceinline__ float tanh_fast(float x) {
    // tanh(x) = 1 - 2/(e^{2x}+1); robust at both tails
    return 1.0f - __fdividef(2.0f, __expf(2.0f * x) + 1.0f);
}

// NOTE: parameter names must not collide with float4 member names (.x/.y/.z/.w)
#define DOT4(acc, W4, V4)                        \
    acc = fmaf((W4).x, (V4).x, acc);             \
    acc = fmaf((W4).y, (V4).y, acc);             \
    acc = fmaf((W4).z, (V4).z, acc);             \
    acc = fmaf((W4).w, (V4).w, acc);

__global__ void __launch_bounds__(NTHREADS, 1) gru_fused_kernel(
    const float* __restrict__ x,
    const float* __restrict__ w_ih0, const float* __restrict__ w_hh0,
    const float* __restrict__ b_ih0, const float* __restrict__ b_hh0,
    const float* __restrict__ w_ih1, const float* __restrict__ w_hh1,
    const float* __restrict__ b_ih1, const float* __restrict__ b_hh1,
    const float* __restrict__ w_cls, const float* __restrict__ b_cls,
    float* __restrict__ out)
{
    extern __shared__ float sm[];
    const int tid = threadIdx.x;

    // ---- cooperative weight load with crosswise float4 swizzle ----
    // logical (u,k) -> phys u*K + (((k4 ^ (u&7))<<2) | (k&3)); conflict-free
    // LDS.128 when lane==u reads its row at a common k4.
    for (int i = tid; i < NG * ND; i += NTHREADS) {
        int u = i >> 6, k = i & 63;
        int k4 = k >> 2, kk = k & 3;
        sm[OFF_WIH0 + u * 64 + (((k4 ^ (u & 7)) << 2) | kk)] = w_ih0[i];
    }
    for (int i = tid; i < NG * NH; i += NTHREADS) {
        int u = i >> 5, k = i & 31;
        int k4 = k >> 2, kk = k & 3;
        int ph = u * 32 + (((k4 ^ (u & 7)) << 2) | kk);
        sm[OFF_WHH0 + ph] = w_hh0[i];
        sm[OFF_WIH1 + ph] = w_ih1[i];
        sm[OFF_WHH1 + ph] = w_hh1[i];
    }
    if (tid < NH) {
        int u = tid;
        sm[OFF_BIAS +   0 + u] = b_ih0[u]      + b_hh0[u];        // r gate combined
        sm[OFF_BIAS +  32 + u] = b_ih0[32 + u] + b_hh0[32 + u];   // z gate combined
        sm[OFF_BIAS +  64 + u] = b_ih0[64 + u];                   // n gate, x side
        sm[OFF_BIAS +  96 + u] = b_hh0[64 + u];                   // n gate, h side
        sm[OFF_BIAS + 128 + u] = b_ih1[u]      + b_hh1[u];
        sm[OFF_BIAS + 160 + u] = b_ih1[32 + u] + b_hh1[32 + u];
        sm[OFF_BIAS + 192 + u] = b_ih1[64 + u];
        sm[OFF_BIAS + 224 + u] = b_hh1[64 + u];
    }
    // zero h0/h1 buffers (contiguous region)
    for (int i = tid; i < 896; i += NTHREADS) sm[OFF_H0 + i] = 0.0f;
    __syncthreads();

    const int wid = tid >> 5, lane = tid & 31;
    const int gw = blockIdx.x * WPB + wid;      // global warp id
    if (gw * 2 >= NB) return;                   // 1024 active warps
    const int row0 = gw * 2;

    float* shx = sm + OFF_X  + wid * 128;       // [2][64]
    float* sh0 = sm + OFF_H0 + wid * 64;        // [2][32]
    float* sh1 = sm + OFF_H1 + wid * 64;        // [2][32]

    const float4* w0  = (const float4*)(sm + OFF_WIH0);  // row stride 16 float4
    const float4* wh0 = (const float4*)(sm + OFF_WHH0);  // row stride 8
    const float4* wi1 = (const float4*)(sm + OFF_WIH1);
    const float4* wh1 = (const float4*)(sm + OFF_WHH1);
    const float* bias = sm + OFF_BIAS;

    const int u = lane, s = lane & 7;

    // x prefetch: 2 rows * 16 float4 = 32 float4 -> one per lane
    const int lrow = lane >> 4;
    const int lk4  = lane & 15;
    const float* xp = x + (size_t)(row0 + lrow) * (NT * ND) + (lk4 << 2);
    float4 xr = *(const float4*)xp;
    xp += ND;

    const float br0v = bias[u],       bz0v = bias[32 + u];
    const float bnx0v = bias[64 + u], bnh0v = bias[96 + u];
    const float br1v = bias[128 + u],  bz1v = bias[160 + u];
    const float bnx1v = bias[192 + u], bnh1v = bias[224 + u];

    // per-lane carried hidden state (this lane's unit, rows 0/1)
    float h0a = 0.0f, h0b = 0.0f, h1a = 0.0f, h1b = 0.0f;

    for (int t = 0; t < NT; ++t) {
        // publish x_t into warp-private smem
        ((float4*)shx)[lrow * 16 + lk4] = xr;
        __syncwarp();
        if (t + 1 < NT) { xr = *(const float4*)xp; xp += ND; }

        // ================= layer 0 =================
        float ar0 = br0v, az0 = bz0v, anx0 = bnx0v, anh0 = bnh0v;
        float ar1 = br0v, az1 = bz0v, anx1 = bnx0v, anh1 = bnh0v;
        {
            const float4* xv = (const float4*)shx;
            #pragma unroll
            for (int k4 = 0; k4 < 16; ++k4) {
                const int p = k4 ^ s;
                float4 wr = w0[u * 16 + p];
                float4 wz = w0[(32 + u) * 16 + p];
                float4 wn = w0[(64 + u) * 16 + p];
                float4 x0 = xv[k4];
                float4 x1 = xv[16 + k4];
                DOT4(ar0, wr, x0); DOT4(az0, wz, x0); DOT4(anx0, wn, x0);
                DOT4(ar1, wr, x1); DOT4(az1, wz, x1); DOT4(anx1, wn, x1);
            }
            const float4* hv = (const float4*)sh0;
            #pragma unroll
            for (int k4 = 0; k4 < 8; ++k4) {
                const int p = k4 ^ s;
                float4 wr = wh0[u * 8 + p];
                float4 wz = wh0[(32 + u) * 8 + p];
                float4 wn = wh0[(64 + u) * 8 + p];
                float4 h0v = hv[k4];
                float4 h1v = hv[8 + k4];
                DOT4(ar0, wr, h0v); DOT4(az0, wz, h0v); DOT4(anh0, wn, h0v);
                DOT4(ar1, wr, h1v); DOT4(az1, wz, h1v); DOT4(anh1, wn, h1v);
            }
        }
        {
            float r0 = sigm(ar0), z0 = sigm(az0);
            float n0 = tanh_fast(fmaf(r0, anh0, anx0));
            h0a = n0 + z0 * (h0a - n0);
            float r1 = sigm(ar1), z1 = sigm(az1);
            float n1 = tanh_fast(fmaf(r1, anh1, anx1));
            h0b = n1 + z1 * (h0b - n1);
        }
        __syncwarp();
        sh0[u] = h0a;
        sh0[32 + u] = h0b;
        __syncwarp();

        // ================= layer 1 =================
        float cr0 = br1v, cz0 = bz1v, cnx0 = bnx1v, cnh0 = bnh1v;
        float cr1 = br1v, cz1 = bz1v, cnx1 = bnx1v, cnh1 = bnh1v;
        {
            const float4* gv = (const float4*)sh0;   // layer-0 output (this step)
            #pragma unroll
            for (int k4 = 0; k4 < 8; ++k4) {
                const int p = k4 ^ s;
                float4 wr = wi1[u * 8 + p];
                float4 wz = wi1[(32 + u) * 8 + p];
                float4 wn = wi1[(64 + u) * 8 + p];
                float4 g0 = gv[k4];
                float4 g1 = gv[8 + k4];
                DOT4(cr0, wr, g0); DOT4(cz0, wz, g0); DOT4(cnx0, wn, g0);
                DOT4(cr1, wr, g1); DOT4(cz1, wz, g1); DOT4(cnx1, wn, g1);
            }
            const float4* qv = (const float4*)sh1;
            #pragma unroll
            for (int k4 = 0; k4 < 8; ++k4) {
                const int p = k4 ^ s;
                float4 wr = wh1[u * 8 + p];
                float4 wz = wh1[(32 + u) * 8 + p];
                float4 wn = wh1[(64 + u) * 8 + p];
                float4 q0 = qv[k4];
                float4 q1 = qv[8 + k4];
                DOT4(cr0, wr, q0); DOT4(cz0, wz, q0); DOT4(cnh0, wn, q0);
                DOT4(cr1, wr, q1); DOT4(cz1, wz, q1); DOT4(cnh1, wn, q1);
            }
        }
        {
            float r0 = sigm(cr0), z0 = sigm(cz0);
            float n0 = tanh_fast(fmaf(r0, cnh0, cnx0));
            h1a = n0 + z0 * (h1a - n0);
            float r1 = sigm(cr1), z1 = sigm(cz1);
            float n1 = tanh_fast(fmaf(r1, cnh1, cnx1));
            h1b = n1 + z1 * (h1b - n1);
        }
        __syncwarp();
        sh1[u] = h1a;
        sh1[32 + u] = h1b;
        __syncwarp();
    }

    // ---- epilogue: hidden states + classifier ----
    // out layout: [0:2048) y, then h_last0 [2048 : 2048+65536), then h_last1
    out[NB + row0 * NH + u]                 = h0a;
    out[NB + (row0 + 1) * NH + u]           = h0b;
    out[NB + NB * NH + row0 * NH + u]       = h1a;
    out[NB + NB * NH + (row0 + 1) * NH + u] = h1b;

    float wc = w_cls[u];
    float p0 = h1a * wc;
    float p1 = h1b * wc;
    #pragma unroll
    for (int o = 16; o > 0; o >>= 1) {
        p0 += __shfl_xor_sync(0xffffffffu, p0, o);
        p1 += __shfl_xor_sync(0xffffffffu, p1, o);
    }
    if (lane == 0) {
        float bc = b_cls[0];
        out[row0]     = sigm(p0 + bc);
        out[row0 + 1] = sigm(p1 + bc);
    }
}

extern "C" void kernel_launch(void* const* d_in, const int* in_sizes, int n_in,
                              void* d_out, int out_size) {
    (void)in_sizes; (void)n_in; (void)out_size;
    cudaFuncSetAttribute(gru_fused_kernel,
                         cudaFuncAttributeMaxDynamicSharedMemorySize,
                         SMEM_FLOATS * sizeof(float));
    gru_fused_kernel<<<NBLK, NTHREADS, SMEM_FLOATS * sizeof(float)>>>(
        (const float*)d_in[0],
        (const float*)d_in[1], (const float*)d_in[2],
        (const float*)d_in[3], (const float*)d_in[4],
        (const float*)d_in[5], (const float*)d_in[6],
        (const float*)d_in[7], (const float*)d_in[8],
        (const float*)d_in[9], (const float*)d_in[10],
        (float*)d_out);
}

// round 6
// speedup vs baseline: 1.3511x; 1.3511x over previous
#include <cuda_runtime.h>
#include <cstdint>

// Problem constants
#define NB 2048   // batch
#define NT 1024   // timesteps
#define ND 64     // input size
#define NH 32     // hidden
#define NG 96     // 3*H

// ---------------- packed f32x2 helpers ----------------
typedef unsigned long long u64t;

__device__ __forceinline__ u64t ffma2(u64t a, u64t b, u64t c) {
    u64t d;
    asm("fma.rn.f32x2 %0, %1, %2, %3;" : "=l"(d) : "l"(a), "l"(b), "l"(c));
    return d;
}
__device__ __forceinline__ u64t pack2(float lo, float hi) {
    u64t d;
    asm("mov.b64 %0, {%1, %2};" : "=l"(d) : "r"(__float_as_uint(lo)), "r"(__float_as_uint(hi)));
    return d;
}
__device__ __forceinline__ u64t dup2(float v) { return pack2(v, v); }
__device__ __forceinline__ float2 unpack2(u64t p) {
    unsigned lo, hi;
    asm("mov.b64 {%0, %1}, %2;" : "=r"(lo), "=r"(hi) : "l"(p));
    return make_float2(__uint_as_float(lo), __uint_as_float(hi));
}

__device__ __forceinline__ float sigm(float x) {
    return __fdividef(1.0f, 1.0f + __expf(-x));
}
__device__ __forceinline__ float tanh_fast(float x) {
    return 1.0f - __fdividef(2.0f, __expf(2.0f * x) + 1.0f);
}

// 805 MB scratch for the precomputed input GEMM: gx[(b*NT + t)*96 + g]
__device__ float g_gx[(size_t)NB * NT * NG];

// ============================================================
// Phase 1: gx[b,t,:] = w_ih0 @ x[b,t,:]   (pure GEMM, parallel)
// Block: 8 warps; each warp handles 8 rows (4 row-pairs).
// ============================================================
#define P1_THREADS 256
#define P1_ROWS_PER_WARP 8
#define P1_ROWS_PER_BLOCK 64
#define P1_BLOCKS ((NB * NT) / P1_ROWS_PER_BLOCK)   // 32768

__global__ void __launch_bounds__(P1_THREADS, 1) gx_gemm_kernel(
    const float* __restrict__ x,
    const float* __restrict__ w_ih0)
{
    // weights swizzled: logical (u,k) -> u*64 + (((k4 ^ (u&7))<<2) | kk)
    __shared__ __align__(16) float ws[NG * ND];            // 6144 floats
    __shared__ __align__(16) float xs_all[8 * 512];        // per-warp pair-interleaved x

    const int tid = threadIdx.x;
    for (int i = tid; i < NG * ND; i += P1_THREADS) {
        int u = i >> 6, k = i & 63;
        int k4 = k >> 2, kk = k & 3;
        ws[u * 64 + (((k4 ^ (u & 7)) << 2) | kk)] = w_ih0[i];
    }
    __syncthreads();

    const int wid = tid >> 5, lane = tid & 31;
    const int u = lane, s = lane & 7;
    float* xs = xs_all + wid * 512;

    const long long R0 = (long long)(blockIdx.x * 8 + wid) * P1_ROWS_PER_WARP;

    // stage 8 rows of x, interleaved by row-pair: xs[p*128 + 2k + e]
    {
        const float4* xg = (const float4*)(x + R0 * ND);   // 128 float4
        #pragma unroll
        for (int i = 0; i < 4; ++i) {
            int j = lane + 32 * i;
            float4 v = xg[j];
            int r = j >> 4, k4 = j & 15;
            float* dst = xs + (r >> 1) * 128 + 8 * k4 + (r & 1);
            dst[0] = v.x; dst[2] = v.y; dst[4] = v.z; dst[6] = v.w;
        }
    }
    __syncwarp();

    u64t accr[4], accz[4], accn[4];
    #pragma unroll
    for (int p = 0; p < 4; ++p) { accr[p] = 0ull; accz[p] = 0ull; accn[p] = 0ull; }

    const float4* ws4 = (const float4*)ws;   // row stride 16 float4
    #pragma unroll
    for (int k4 = 0; k4 < 16; ++k4) {
        const int pp = k4 ^ s;
        float4 wr = ws4[u * 16 + pp];
        float4 wz = ws4[(32 + u) * 16 + pp];
        float4 wn = ws4[(64 + u) * 16 + pp];
        u64t dr0 = dup2(wr.x), dr1 = dup2(wr.y), dr2 = dup2(wr.z), dr3 = dup2(wr.w);
        u64t dz0 = dup2(wz.x), dz1 = dup2(wz.y), dz2 = dup2(wz.z), dz3 = dup2(wz.w);
        u64t dn0 = dup2(wn.x), dn1 = dup2(wn.y), dn2 = dup2(wn.z), dn3 = dup2(wn.w);
        #pragma unroll
        for (int p = 0; p < 4; ++p) {
            const ulonglong2* vp = (const ulonglong2*)(xs + p * 128 + 8 * k4);
            ulonglong2 v01 = vp[0];   // pairs for k=4k4, 4k4+1
            ulonglong2 v23 = vp[1];   // pairs for k=4k4+2, 4k4+3
            accr[p] = ffma2(dr0, v01.x, accr[p]); accr[p] = ffma2(dr1, v01.y, accr[p]);
            accr[p] = ffma2(dr2, v23.x, accr[p]); accr[p] = ffma2(dr3, v23.y, accr[p]);
            accz[p] = ffma2(dz0, v01.x, accz[p]); accz[p] = ffma2(dz1, v01.y, accz[p]);
            accz[p] = ffma2(dz2, v23.x, accz[p]); accz[p] = ffma2(dz3, v23.y, accz[p]);
            accn[p] = ffma2(dn0, v01.x, accn[p]); accn[p] = ffma2(dn1, v01.y, accn[p]);
            accn[p] = ffma2(dn2, v23.x, accn[p]); accn[p] = ffma2(dn3, v23.y, accn[p]);
        }
    }

    #pragma unroll
    for (int p = 0; p < 4; ++p) {
        float2 fr = unpack2(accr[p]);
        float2 fz = unpack2(accz[p]);
        float2 fn = unpack2(accn[p]);
        float* o0 = g_gx + (size_t)(R0 + 2 * p) * NG;
        float* o1 = o0 + NG;
        o0[u] = fr.x;  o0[32 + u] = fz.x;  o0[64 + u] = fn.x;
        o1[u] = fr.y;  o1[32 + u] = fz.y;  o1[64 + u] = fn.y;
    }
}

// ============================================================
// Phase 2: recurrent loop. 148 blocks x 7 warps, 2 rows/warp.
// h stored as row-pair-interleaved f32x2 in warp-private smem.
// w_ih1 cached in registers; whh0/wh1 in swizzled smem.
// ============================================================
#define WPB 7
#define NBLK 148
#define NTHREADS (WPB * 32)

__global__ void __launch_bounds__(NTHREADS, 1) gru_recurrent_kernel(
    const float* __restrict__ w_hh0,
    const float* __restrict__ b_ih0, const float* __restrict__ b_hh0,
    const float* __restrict__ w_ih1, const float* __restrict__ w_hh1,
    const float* __restrict__ b_ih1, const float* __restrict__ b_hh1,
    const float* __restrict__ w_cls, const float* __restrict__ b_cls,
    float* __restrict__ out)
{
    __shared__ __align__(16) float whh0s[NG * NH];   // 3072, swizzled
    __shared__ __align__(16) float wh1s[NG * NH];    // 3072, swizzled
    __shared__ __align__(16) float sh0_all[WPB * 64];  // pairs (h row0,row1) per unit
    __shared__ __align__(16) float sh1_all[WPB * 64];

    const int tid = threadIdx.x;
    for (int i = tid; i < NG * NH; i += NTHREADS) {
        int g = i >> 5, k = i & 31;
        int k4 = k >> 2, kk = k & 3;
        int ph = g * 32 + (((k4 ^ (g & 7)) << 2) | kk);
        whh0s[ph] = w_hh0[i];
        wh1s[ph]  = w_hh1[i];
    }
    for (int i = tid; i < WPB * 64; i += NTHREADS) {
        sh0_all[i] = 0.0f;
        sh1_all[i] = 0.0f;
    }
    __syncthreads();

    const int wid = tid >> 5, lane = tid & 31;
    const int gw = blockIdx.x * WPB + wid;
    if (gw * 2 >= NB) return;
    const int row0 = gw * 2;
    const int u = lane, s = lane & 7;

    float* sh0 = sh0_all + wid * 64;
    float* sh1 = sh1_all + wid * 64;

    // register-cache w_ih1 (rows u, 32+u, 64+u)
    float4 wi1r[8], wi1z[8], wi1n[8];
    {
        const float4* a = (const float4*)(w_ih1 + u * NH);
        const float4* b = (const float4*)(w_ih1 + (32 + u) * NH);
        const float4* c = (const float4*)(w_ih1 + (64 + u) * NH);
        #pragma unroll
        for (int i = 0; i < 8; ++i) { wi1r[i] = a[i]; wi1z[i] = b[i]; wi1n[i] = c[i]; }
    }

    // per-lane biases
    const float br0v  = b_ih0[u]      + b_hh0[u];
    const float bz0v  = b_ih0[32 + u] + b_hh0[32 + u];
    const float bnx0v = b_ih0[64 + u];
    const float bnh0v = b_hh0[64 + u];
    const float br1v  = b_ih1[u]      + b_hh1[u];
    const float bz1v  = b_ih1[32 + u] + b_hh1[32 + u];
    const float bnx1v = b_ih1[64 + u];
    const float bnh1v = b_hh1[64 + u];

    const float* gx0 = g_gx + (size_t)row0 * NT * NG;
    const float* gx1 = gx0 + (size_t)NT * NG;

    // prefetch gx for t=0 (6 floats/lane)
    float p0r = gx0[u], p0z = gx0[32 + u], p0n = gx0[64 + u];
    float p1r = gx1[u], p1z = gx1[32 + u], p1n = gx1[64 + u];

    float h0a = 0.0f, h0b = 0.0f, h1a = 0.0f, h1b = 0.0f;

    const float4* whh0s4 = (const float4*)whh0s;  // row stride 8 float4
    const float4* wh1s4  = (const float4*)wh1s;

    for (int t = 0; t < NT; ++t) {
        // ---- layer 0 ----
        u64t ar  = pack2(br0v  + p0r, br0v  + p1r);
        u64t az  = pack2(bz0v  + p0z, bz0v  + p1z);
        u64t anx = pack2(bnx0v + p0n, bnx0v + p1n);
        u64t anh = dup2(bnh0v);

        // prefetch next step's gx
        if (t + 1 < NT) {
            const float* q0 = gx0 + (size_t)(t + 1) * NG;
            const float* q1 = gx1 + (size_t)(t + 1) * NG;
            p0r = q0[u]; p0z = q0[32 + u]; p0n = q0[64 + u];
            p1r = q1[u]; p1z = q1[32 + u]; p1n = q1[64 + u];
        }

        {
            const ulonglong2* hp = (const ulonglong2*)sh0;
            #pragma unroll
            for (int i = 0; i < 8; ++i) {
                const int pp = i ^ s;
                float4 wr = whh0s4[u * 8 + pp];
                float4 wz = whh0s4[(32 + u) * 8 + pp];
                float4 wn = whh0s4[(64 + u) * 8 + pp];
                ulonglong2 v01 = hp[2 * i];
                ulonglong2 v23 = hp[2 * i + 1];
                ar  = ffma2(dup2(wr.x), v01.x, ar);  ar  = ffma2(dup2(wr.y), v01.y, ar);
                ar  = ffma2(dup2(wr.z), v23.x, ar);  ar  = ffma2(dup2(wr.w), v23.y, ar);
                az  = ffma2(dup2(wz.x), v01.x, az);  az  = ffma2(dup2(wz.y), v01.y, az);
                az  = ffma2(dup2(wz.z), v23.x, az);  az  = ffma2(dup2(wz.w), v23.y, az);
                anh = ffma2(dup2(wn.x), v01.x, anh); anh = ffma2(dup2(wn.y), v01.y, anh);
                anh = ffma2(dup2(wn.z), v23.x, anh); anh = ffma2(dup2(wn.w), v23.y, anh);
            }
        }
        {
            float2 fr = unpack2(ar), fz = unpack2(az);
            float2 fnx = unpack2(anx), fnh = unpack2(anh);
            float r0 = sigm(fr.x), z0 = sigm(fz.x);
            float n0 = tanh_fast(fmaf(r0, fnh.x, fnx.x));
            h0a = n0 + z0 * (h0a - n0);
            float r1 = sigm(fr.y), z1 = sigm(fz.y);
            float n1 = tanh_fast(fmaf(r1, fnh.y, fnx.y));
            h0b = n1 + z1 * (h0b - n1);
        }
        __syncwarp();
        ((float2*)sh0)[u] = make_float2(h0a, h0b);
        __syncwarp();

        // ---- layer 1 ----
        u64t cr  = dup2(br1v);
        u64t cz  = dup2(bz1v);
        u64t cnx = dup2(bnx1v);
        u64t cnh = dup2(bnh1v);
        {
            const ulonglong2* gp = (const ulonglong2*)sh0;  // new layer-0 output
            const ulonglong2* qp = (const ulonglong2*)sh1;  // previous h1
            #pragma unroll
            for (int i = 0; i < 8; ++i) {
                ulonglong2 g01 = gp[2 * i];
                ulonglong2 g23 = gp[2 * i + 1];
                float4 wr = wi1r[i], wz = wi1z[i], wn = wi1n[i];
                cr  = ffma2(dup2(wr.x), g01.x, cr);  cr  = ffma2(dup2(wr.y), g01.y, cr);
                cr  = ffma2(dup2(wr.z), g23.x, cr);  cr  = ffma2(dup2(wr.w), g23.y, cr);
                cz  = ffma2(dup2(wz.x), g01.x, cz);  cz  = ffma2(dup2(wz.y), g01.y, cz);
                cz  = ffma2(dup2(wz.z), g23.x, cz);  cz  = ffma2(dup2(wz.w), g23.y, cz);
                cnx = ffma2(dup2(wn.x), g01.x, cnx); cnx = ffma2(dup2(wn.y), g01.y, cnx);
                cnx = ffma2(dup2(wn.z), g23.x, cnx); cnx = ffma2(dup2(wn.w), g23.y, cnx);

                const int pp = i ^ s;
                float4 vr = wh1s4[u * 8 + pp];
                float4 vz = wh1s4[(32 + u) * 8 + pp];
                float4 vn = wh1s4[(64 + u) * 8 + pp];
                ulonglong2 q01 = qp[2 * i];
                ulonglong2 q23 = qp[2 * i + 1];
                cr  = ffma2(dup2(vr.x), q01.x, cr);  cr  = ffma2(dup2(vr.y), q01.y, cr);
                cr  = ffma2(dup2(vr.z), q23.x, cr);  cr  = ffma2(dup2(vr.w), q23.y, cr);
                cz  = ffma2(dup2(vz.x), q01.x, cz);  cz  = ffma2(dup2(vz.y), q01.y, cz);
                cz  = ffma2(dup2(vz.z), q23.x, cz);  cz  = ffma2(dup2(vz.w), q23.y, cz);
                cnh = ffma2(dup2(vn.x), q01.x, cnh); cnh = ffma2(dup2(vn.y), q01.y, cnh);
                cnh = ffma2(dup2(vn.z), q23.x, cnh); cnh = ffma2(dup2(vn.w), q23.y, cnh);
            }
        }
        {
            float2 fr = unpack2(cr), fz = unpack2(cz);
            float2 fnx = unpack2(cnx), fnh = unpack2(cnh);
            float r0 = sigm(fr.x), z0 = sigm(fz.x);
            float n0 = tanh_fast(fmaf(r0, fnh.x, fnx.x));
            h1a = n0 + z0 * (h1a - n0);
            float r1 = sigm(fr.y), z1 = sigm(fz.y);
            float n1 = tanh_fast(fmaf(r1, fnh.y, fnx.y));
            h1b = n1 + z1 * (h1b - n1);
        }
        __syncwarp();
        ((float2*)sh1)[u] = make_float2(h1a, h1b);
        __syncwarp();
    }

    // ---- epilogue: hidden states + classifier ----
    out[NB + row0 * NH + u]                 = h0a;
    out[NB + (row0 + 1) * NH + u]           = h0b;
    out[NB + NB * NH + row0 * NH + u]       = h1a;
    out[NB + NB * NH + (row0 + 1) * NH + u] = h1b;

    float wc = w_cls[u];
    float q0 = h1a * wc;
    float q1 = h1b * wc;
    #pragma unroll
    for (int o = 16; o > 0; o >>= 1) {
        q0 += __shfl_xor_sync(0xffffffffu, q0, o);
        q1 += __shfl_xor_sync(0xffffffffu, q1, o);
    }
    if (lane == 0) {
        float bc = b_cls[0];
        out[row0]     = sigm(q0 + bc);
        out[row0 + 1] = sigm(q1 + bc);
    }
}

extern "C" void kernel_launch(void* const* d_in, const int* in_sizes, int n_in,
                              void* d_out, int out_size) {
    (void)in_sizes; (void)n_in; (void)out_size;
    const float* x     = (const float*)d_in[0];
    const float* w_ih0 = (const float*)d_in[1];
    const float* w_hh0 = (const float*)d_in[2];
    const float* b_ih0 = (const float*)d_in[3];
    const float* b_hh0 = (const float*)d_in[4];
    const float* w_ih1 = (const float*)d_in[5];
    const float* w_hh1 = (const float*)d_in[6];
    const float* b_ih1 = (const float*)d_in[7];
    const float* b_hh1 = (const float*)d_in[8];
    const float* w_cls = (const float*)d_in[9];
    const float* b_cls = (const float*)d_in[10];

    gx_gemm_kernel<<<P1_BLOCKS, P1_THREADS>>>(x, w_ih0);
    gru_recurrent_kernel<<<NBLK, NTHREADS>>>(
        w_hh0, b_ih0, b_hh0, w_ih1, w_hh1, b_ih1, b_hh1,
        w_cls, b_cls, (float*)d_out);
}

// round 7
// speedup vs baseline: 1.5258x; 1.1293x over previous
#include <cuda_runtime.h>
#include <cstdint>

// Problem constants
#define NB 2048   // batch
#define NT 1024   // timesteps
#define ND 64     // input size
#define NH 32     // hidden
#define NG 96     // 3*H

// ---------------- packed f32x2 helpers ----------------
typedef unsigned long long u64t;

__device__ __forceinline__ u64t ffma2(u64t a, u64t b, u64t c) {
    u64t d;
    asm("fma.rn.f32x2 %0, %1, %2, %3;" : "=l"(d) : "l"(a), "l"(b), "l"(c));
    return d;
}
__device__ __forceinline__ u64t add2(u64t a, u64t b) {
    u64t d;
    asm("add.rn.f32x2 %0, %1, %2;" : "=l"(d) : "l"(a), "l"(b));
    return d;
}
__device__ __forceinline__ u64t pack2(float lo, float hi) {
    u64t d;
    asm("mov.b64 %0, {%1, %2};" : "=l"(d) : "r"(__float_as_uint(lo)), "r"(__float_as_uint(hi)));
    return d;
}
__device__ __forceinline__ u64t dup2(float v) { return pack2(v, v); }
__device__ __forceinline__ float2 unpack2(u64t p) {
    unsigned lo, hi;
    asm("mov.b64 {%0, %1}, %2;" : "=r"(lo), "=r"(hi) : "l"(p));
    return make_float2(__uint_as_float(lo), __uint_as_float(hi));
}

__device__ __forceinline__ float sigm(float x) {
    return __fdividef(1.0f, 1.0f + __expf(-x));
}
__device__ __forceinline__ float tanh_fast(float x) {
    return 1.0f - __fdividef(2.0f, __expf(2.0f * x) + 1.0f);
}

// Scratch: gx pre-activations, batch-pair interleaved f32x2.
// g_gx[((b/2)*NT + t)*96 + g] = pair( row 2*(b/2) value, row 2*(b/2)+1 value )
__device__ u64t g_gx[(size_t)(NB / 2) * NT * NG];

// ============================================================
// Phase 1 (persistent): gx = w_ih0 @ x  for all (b,t)
// 148 blocks x 8 warps; tile = 2 batches x 4 timesteps (8 rows).
// ============================================================
#define P1_THREADS 256
#define P1_BLOCKS 148
#define P1_WARPS (P1_BLOCKS * 8)                 // 1184
#define P1_NTILES ((NB / 2) * (NT / 4))          // 262144

__global__ void __launch_bounds__(P1_THREADS, 1) gx_gemm_kernel(
    const float* __restrict__ x,
    const float* __restrict__ w_ih0)
{
    __shared__ __align__(16) float ws[NG * ND];       // swizzled weights
    __shared__ __align__(16) float xs_all[8 * 512];   // per-warp pair-interleaved x

    const int tid = threadIdx.x;
    for (int i = tid; i < NG * ND; i += P1_THREADS) {
        int uu = i >> 6, k = i & 63;
        int k4 = k >> 2, kk = k & 3;
        ws[uu * 64 + (((k4 ^ (uu & 7)) << 2) | kk)] = w_ih0[i];
    }
    __syncthreads();

    const int wid = tid >> 5, lane = tid & 31;
    const int u = lane, s = lane & 7;
    float* xs = xs_all + wid * 512;
    const float4* ws4 = (const float4*)ws;   // row stride 16 float4

    const int gwarp = blockIdx.x * 8 + wid;

    float4 v[4];
    // preload first tile
    {
        int pb = gwarp >> 8, tt = (gwarp & 255) << 2;
        const float4* bb0 = (const float4*)(x + ((size_t)(2 * pb) * NT + tt) * ND);
        const float4* bb1 = (const float4*)(x + ((size_t)(2 * pb + 1) * NT + tt) * ND);
        #pragma unroll
        for (int i = 0; i < 4; ++i) {
            int j = lane + 32 * i;
            v[i] = (j >= 64) ? bb1[j & 63] : bb0[j];
        }
    }

    for (int T = gwarp; T < P1_NTILES; T += P1_WARPS) {
        const int pb = T >> 8, tt = (T & 255) << 2;

        // stage current tile (pair-interleaved): xs[t_loc*128 + 8*k4 + e]
        __syncwarp();
        #pragma unroll
        for (int i = 0; i < 4; ++i) {
            int j = lane + 32 * i;
            int e = j >> 6, jj = j & 63;
            int t_loc = jj >> 4, k4 = jj & 15;
            float* dst = xs + t_loc * 128 + 8 * k4 + e;
            dst[0] = v[i].x; dst[2] = v[i].y; dst[4] = v[i].z; dst[6] = v[i].w;
        }
        __syncwarp();

        // prefetch next tile while computing
        const int Tn = T + P1_WARPS;
        if (Tn < P1_NTILES) {
            int pbn = Tn >> 8, ttn = (Tn & 255) << 2;
            const float4* bb0 = (const float4*)(x + ((size_t)(2 * pbn) * NT + ttn) * ND);
            const float4* bb1 = (const float4*)(x + ((size_t)(2 * pbn + 1) * NT + ttn) * ND);
            #pragma unroll
            for (int i = 0; i < 4; ++i) {
                int j = lane + 32 * i;
                v[i] = (j >= 64) ? bb1[j & 63] : bb0[j];
            }
        }

        u64t accr[4], accz[4], accn[4];
        #pragma unroll
        for (int p = 0; p < 4; ++p) { accr[p] = 0ull; accz[p] = 0ull; accn[p] = 0ull; }

        #pragma unroll
        for (int k4 = 0; k4 < 16; ++k4) {
            const int pp = k4 ^ s;
            float4 wr = ws4[u * 16 + pp];
            float4 wz = ws4[(32 + u) * 16 + pp];
            float4 wn = ws4[(64 + u) * 16 + pp];
            u64t dr0 = dup2(wr.x), dr1 = dup2(wr.y), dr2 = dup2(wr.z), dr3 = dup2(wr.w);
            u64t dz0 = dup2(wz.x), dz1 = dup2(wz.y), dz2 = dup2(wz.z), dz3 = dup2(wz.w);
            u64t dn0 = dup2(wn.x), dn1 = dup2(wn.y), dn2 = dup2(wn.z), dn3 = dup2(wn.w);
            #pragma unroll
            for (int p = 0; p < 4; ++p) {
                const ulonglong2* vp = (const ulonglong2*)(xs + p * 128 + 8 * k4);
                ulonglong2 v01 = vp[0];
                ulonglong2 v23 = vp[1];
                accr[p] = ffma2(dr0, v01.x, accr[p]); accr[p] = ffma2(dr1, v01.y, accr[p]);
                accr[p] = ffma2(dr2, v23.x, accr[p]); accr[p] = ffma2(dr3, v23.y, accr[p]);
                accz[p] = ffma2(dz0, v01.x, accz[p]); accz[p] = ffma2(dz1, v01.y, accz[p]);
                accz[p] = ffma2(dz2, v23.x, accz[p]); accz[p] = ffma2(dz3, v23.y, accz[p]);
                accn[p] = ffma2(dn0, v01.x, accn[p]); accn[p] = ffma2(dn1, v01.y, accn[p]);
                accn[p] = ffma2(dn2, v23.x, accn[p]); accn[p] = ffma2(dn3, v23.y, accn[p]);
            }
        }

        #pragma unroll
        for (int p = 0; p < 4; ++p) {
            u64t* o = g_gx + ((size_t)pb * NT + tt + p) * NG;
            o[u]      = accr[p];
            o[32 + u] = accz[p];
            o[64 + u] = accn[p];
        }
    }
}

// ============================================================
// Phase 2: recurrence. 128 blocks x 4 warps, 4 rows/warp
// (two f32x2 pair-buffers A,B). wi1 register-cached.
// ============================================================
#define WPB2 4
#define NBLK2 128
#define NTHR2 (WPB2 * 32)

__global__ void __launch_bounds__(NTHR2, 1) gru_recurrent_kernel(
    const float* __restrict__ w_hh0,
    const float* __restrict__ b_ih0, const float* __restrict__ b_hh0,
    const float* __restrict__ w_ih1, const float* __restrict__ w_hh1,
    const float* __restrict__ b_ih1, const float* __restrict__ b_hh1,
    const float* __restrict__ w_cls, const float* __restrict__ b_cls,
    float* __restrict__ out)
{
    __shared__ __align__(16) float whh0s[NG * NH];    // swizzled
    __shared__ __align__(16) float wh1s[NG * NH];     // swizzled
    __shared__ __align__(16) u64t sh0u_all[WPB2 * 64];  // [warp][A:0..31 | B:32..63]
    __shared__ __align__(16) u64t sh1u_all[WPB2 * 64];

    const int tid = threadIdx.x;
    for (int i = tid; i < NG * NH; i += NTHR2) {
        int g = i >> 5, k = i & 31;
        int k4 = k >> 2, kk = k & 3;
        int ph = g * 32 + (((k4 ^ (g & 7)) << 2) | kk);
        whh0s[ph] = w_hh0[i];
        wh1s[ph]  = w_hh1[i];
    }
    for (int i = tid; i < WPB2 * 64; i += NTHR2) {
        sh0u_all[i] = 0ull;
        sh1u_all[i] = 0ull;
    }
    __syncthreads();

    const int wid = tid >> 5, lane = tid & 31;
    const int q = blockIdx.x * WPB2 + wid;   // 0..511
    const int b0 = q * 4;
    const int u = lane, s = lane & 7;

    u64t* sh0u = sh0u_all + wid * 64;
    u64t* sh1u = sh1u_all + wid * 64;

    // register-cache w_ih1 rows u, 32+u, 64+u
    float4 wi1r[8], wi1z[8], wi1n[8];
    {
        const float4* a = (const float4*)(w_ih1 + u * NH);
        const float4* b = (const float4*)(w_ih1 + (32 + u) * NH);
        const float4* c = (const float4*)(w_ih1 + (64 + u) * NH);
        #pragma unroll
        for (int i = 0; i < 8; ++i) { wi1r[i] = a[i]; wi1z[i] = b[i]; wi1n[i] = c[i]; }
    }

    const u64t br0d  = dup2(b_ih0[u]      + b_hh0[u]);
    const u64t bz0d  = dup2(b_ih0[32 + u] + b_hh0[32 + u]);
    const u64t bnx0d = dup2(b_ih0[64 + u]);
    const u64t bnh0d = dup2(b_hh0[64 + u]);
    const u64t br1d  = dup2(b_ih1[u]      + b_hh1[u]);
    const u64t bz1d  = dup2(b_ih1[32 + u] + b_hh1[32 + u]);
    const u64t bnx1d = dup2(b_ih1[64 + u]);
    const u64t bnh1d = dup2(b_hh1[64 + u]);

    // gx streams: pairbuf A = batches (4q, 4q+1) -> pr = 2q; B -> pr = 2q+1
    const u64t* gxA = g_gx + (size_t)(2 * q) * NT * NG;
    const u64t* gxB = gxA + (size_t)NT * NG;

    u64t pAr = gxA[u], pAz = gxA[32 + u], pAn = gxA[64 + u];
    u64t pBr = gxB[u], pBz = gxB[32 + u], pBn = gxB[64 + u];

    float hA0 = 0.0f, hA1 = 0.0f, hB0 = 0.0f, hB1 = 0.0f;   // layer0 h
    float jA0 = 0.0f, jA1 = 0.0f, jB0 = 0.0f, jB1 = 0.0f;   // layer1 h

    const float4* whh0s4 = (const float4*)whh0s;
    const float4* wh1s4  = (const float4*)wh1s;
    const ulonglong2* hpA = (const ulonglong2*)sh0u;
    const ulonglong2* hpB = (const ulonglong2*)(sh0u + 32);
    const ulonglong2* qpA = (const ulonglong2*)sh1u;
    const ulonglong2* qpB = (const ulonglong2*)(sh1u + 32);

    for (int t = 0; t < NT; ++t) {
        // ---------------- layer 0 ----------------
        u64t arA = add2(br0d, pAr), azA = add2(bz0d, pAz), anxA = add2(bnx0d, pAn);
        u64t arB = add2(br0d, pBr), azB = add2(bz0d, pBz), anxB = add2(bnx0d, pBn);
        u64t anhA = bnh0d, anhB = bnh0d;

        if (t + 1 < NT) {
            const u64t* a = gxA + (size_t)(t + 1) * NG;
            const u64t* b = gxB + (size_t)(t + 1) * NG;
            pAr = a[u]; pAz = a[32 + u]; pAn = a[64 + u];
            pBr = b[u]; pBz = b[32 + u]; pBn = b[64 + u];
        }

        #pragma unroll
        for (int i = 0; i < 8; ++i) {
            const int pp = i ^ s;
            float4 wr = whh0s4[u * 8 + pp];
            float4 wz = whh0s4[(32 + u) * 8 + pp];
            float4 wn = whh0s4[(64 + u) * 8 + pp];
            u64t r0 = dup2(wr.x), r1 = dup2(wr.y), r2 = dup2(wr.z), r3 = dup2(wr.w);
            u64t z0 = dup2(wz.x), z1 = dup2(wz.y), z2 = dup2(wz.z), z3 = dup2(wz.w);
            u64t n0 = dup2(wn.x), n1 = dup2(wn.y), n2 = dup2(wn.z), n3 = dup2(wn.w);
            ulonglong2 a01 = hpA[2 * i], a23 = hpA[2 * i + 1];
            ulonglong2 b01 = hpB[2 * i], b23 = hpB[2 * i + 1];
            arA  = ffma2(r0, a01.x, arA);  arA  = ffma2(r1, a01.y, arA);
            arA  = ffma2(r2, a23.x, arA);  arA  = ffma2(r3, a23.y, arA);
            azA  = ffma2(z0, a01.x, azA);  azA  = ffma2(z1, a01.y, azA);
            azA  = ffma2(z2, a23.x, azA);  azA  = ffma2(z3, a23.y, azA);
            anhA = ffma2(n0, a01.x, anhA); anhA = ffma2(n1, a01.y, anhA);
            anhA = ffma2(n2, a23.x, anhA); anhA = ffma2(n3, a23.y, anhA);
            arB  = ffma2(r0, b01.x, arB);  arB  = ffma2(r1, b01.y, arB);
            arB  = ffma2(r2, b23.x, arB);  arB  = ffma2(r3, b23.y, arB);
            azB  = ffma2(z0, b01.x, azB);  azB  = ffma2(z1, b01.y, azB);
            azB  = ffma2(z2, b23.x, azB);  azB  = ffma2(z3, b23.y, azB);
            anhB = ffma2(n0, b01.x, anhB); anhB = ffma2(n1, b01.y, anhB);
            anhB = ffma2(n2, b23.x, anhB); anhB = ffma2(n3, b23.y, anhB);
        }
        {
            float2 fr = unpack2(arA), fz = unpack2(azA);
            float2 fnx = unpack2(anxA), fnh = unpack2(anhA);
            float r0 = sigm(fr.x), z0 = sigm(fz.x);
            float n0 = tanh_fast(fmaf(r0, fnh.x, fnx.x));
            hA0 = n0 + z0 * (hA0 - n0);
            float r1 = sigm(fr.y), z1 = sigm(fz.y);
            float n1 = tanh_fast(fmaf(r1, fnh.y, fnx.y));
            hA1 = n1 + z1 * (hA1 - n1);
        }
        {
            float2 fr = unpack2(arB), fz = unpack2(azB);
            float2 fnx = unpack2(anxB), fnh = unpack2(anhB);
            float r0 = sigm(fr.x), z0 = sigm(fz.x);
            float n0 = tanh_fast(fmaf(r0, fnh.x, fnx.x));
            hB0 = n0 + z0 * (hB0 - n0);
            float r1 = sigm(fr.y), z1 = sigm(fz.y);
            float n1 = tanh_fast(fmaf(r1, fnh.y, fnx.y));
            hB1 = n1 + z1 * (hB1 - n1);
        }
        __syncwarp();
        sh0u[u]      = pack2(hA0, hA1);
        sh0u[32 + u] = pack2(hB0, hB1);
        __syncwarp();

        // ---------------- layer 1 ----------------
        u64t crA = br1d, czA = bz1d, cnxA = bnx1d, cnhA = bnh1d;
        u64t crB = br1d, czB = bz1d, cnxB = bnx1d, cnhB = bnh1d;

        #pragma unroll
        for (int i = 0; i < 8; ++i) {
            // input contribution (w_ih1 from registers, g = new layer-0 h)
            {
                float4 wr = wi1r[i], wz = wi1z[i], wn = wi1n[i];
                u64t r0 = dup2(wr.x), r1 = dup2(wr.y), r2 = dup2(wr.z), r3 = dup2(wr.w);
                u64t z0 = dup2(wz.x), z1 = dup2(wz.y), z2 = dup2(wz.z), z3 = dup2(wz.w);
                u64t n0 = dup2(wn.x), n1 = dup2(wn.y), n2 = dup2(wn.z), n3 = dup2(wn.w);
                ulonglong2 a01 = hpA[2 * i], a23 = hpA[2 * i + 1];
                ulonglong2 b01 = hpB[2 * i], b23 = hpB[2 * i + 1];
                crA  = ffma2(r0, a01.x, crA);  crA  = ffma2(r1, a01.y, crA);
                crA  = ffma2(r2, a23.x, crA);  crA  = ffma2(r3, a23.y, crA);
                czA  = ffma2(z0, a01.x, czA);  czA  = ffma2(z1, a01.y, czA);
                czA  = ffma2(z2, a23.x, czA);  czA  = ffma2(z3, a23.y, czA);
                cnxA = ffma2(n0, a01.x, cnxA); cnxA = ffma2(n1, a01.y, cnxA);
                cnxA = ffma2(n2, a23.x, cnxA); cnxA = ffma2(n3, a23.y, cnxA);
                crB  = ffma2(r0, b01.x, crB);  crB  = ffma2(r1, b01.y, crB);
                crB  = ffma2(r2, b23.x, crB);  crB  = ffma2(r3, b23.y, crB);
                czB  = ffma2(z0, b01.x, czB);  czB  = ffma2(z1, b01.y, czB);
                czB  = ffma2(z2, b23.x, czB);  czB  = ffma2(z3, b23.y, czB);
                cnxB = ffma2(n0, b01.x, cnxB); cnxB = ffma2(n1, b01.y, cnxB);
                cnxB = ffma2(n2, b23.x, cnxB); cnxB = ffma2(n3, b23.y, cnxB);
            }
            // hidden contribution (w_hh1 from smem, q = previous layer-1 h)
            {
                const int pp = i ^ s;
                float4 wr = wh1s4[u * 8 + pp];
                float4 wz = wh1s4[(32 + u) * 8 + pp];
                float4 wn = wh1s4[(64 + u) * 8 + pp];
                u64t r0 = dup2(wr.x), r1 = dup2(wr.y), r2 = dup2(wr.z), r3 = dup2(wr.w);
                u64t z0 = dup2(wz.x), z1 = dup2(wz.y), z2 = dup2(wz.z), z3 = dup2(wz.w);
                u64t n0 = dup2(wn.x), n1 = dup2(wn.y), n2 = dup2(wn.z), n3 = dup2(wn.w);
                ulonglong2 a01 = qpA[2 * i], a23 = qpA[2 * i + 1];
                ulonglong2 b01 = qpB[2 * i], b23 = qpB[2 * i + 1];
                crA  = ffma2(r0, a01.x, crA);  crA  = ffma2(r1, a01.y, crA);
                crA  = ffma2(r2, a23.x, crA);  crA  = ffma2(r3, a23.y, crA);
                czA  = ffma2(z0, a01.x, czA);  czA  = ffma2(z1, a01.y, czA);
                czA  = ffma2(z2, a23.x, czA);  czA  = ffma2(z3, a23.y, czA);
                cnhA = ffma2(n0, a01.x, cnhA); cnhA = ffma2(n1, a01.y, cnhA);
                cnhA = ffma2(n2, a23.x, cnhA); cnhA = ffma2(n3, a23.y, cnhA);
                crB  = ffma2(r0, b01.x, crB);  crB  = ffma2(r1, b01.y, crB);
                crB  = ffma2(r2, b23.x, crB);  crB  = ffma2(r3, b23.y, crB);
                czB  = ffma2(z0, b01.x, czB);  czB  = ffma2(z1, b01.y, czB);
                czB  = ffma2(z2, b23.x, czB);  czB  = ffma2(z3, b23.y, czB);
                cnhB = ffma2(n0, b01.x, cnhB); cnhB = ffma2(n1, b01.y, cnhB);
                cnhB = ffma2(n2, b23.x, cnhB); cnhB = ffma2(n3, b23.y, cnhB);
            }
        }
        {
            float2 fr = unpack2(crA), fz = unpack2(czA);
            float2 fnx = unpack2(cnxA), fnh = unpack2(cnhA);
            float r0 = sigm(fr.x), z0 = sigm(fz.x);
            float n0 = tanh_fast(fmaf(r0, fnh.x, fnx.x));
            jA0 = n0 + z0 * (jA0 - n0);
            float r1 = sigm(fr.y), z1 = sigm(fz.y);
            float n1 = tanh_fast(fmaf(r1, fnh.y, fnx.y));
            jA1 = n1 + z1 * (jA1 - n1);
        }
        {
            float2 fr = unpack2(crB), fz = unpack2(czB);
            float2 fnx = unpack2(cnxB), fnh = unpack2(cnhB);
            float r0 = sigm(fr.x), z0 = sigm(fz.x);
            float n0 = tanh_fast(fmaf(r0, fnh.x, fnx.x));
            jB0 = n0 + z0 * (jB0 - n0);
            float r1 = sigm(fr.y), z1 = sigm(fz.y);
            float n1 = tanh_fast(fmaf(r1, fnh.y, fnx.y));
            jB1 = n1 + z1 * (jB1 - n1);
        }
        __syncwarp();
        sh1u[u]      = pack2(jA0, jA1);
        sh1u[32 + u] = pack2(jB0, jB1);
        __syncwarp();
    }

    // ---- epilogue: hidden states + classifier ----
    out[NB + (b0 + 0) * NH + u] = hA0;
    out[NB + (b0 + 1) * NH + u] = hA1;
    out[NB + (b0 + 2) * NH + u] = hB0;
    out[NB + (b0 + 3) * NH + u] = hB1;
    out[NB + NB * NH + (b0 + 0) * NH + u] = jA0;
    out[NB + NB * NH + (b0 + 1) * NH + u] = jA1;
    out[NB + NB * NH + (b0 + 2) * NH + u] = jB0;
    out[NB + NB * NH + (b0 + 3) * NH + u] = jB1;

    float wc = w_cls[u];
    float p0 = jA0 * wc, p1 = jA1 * wc, p2 = jB0 * wc, p3 = jB1 * wc;
    #pragma unroll
    for (int o = 16; o > 0; o >>= 1) {
        p0 += __shfl_xor_sync(0xffffffffu, p0, o);
        p1 += __shfl_xor_sync(0xffffffffu, p1, o);
        p2 += __shfl_xor_sync(0xffffffffu, p2, o);
        p3 += __shfl_xor_sync(0xffffffffu, p3, o);
    }
    if (lane == 0) {
        float bc = b_cls[0];
        out[b0 + 0] = sigm(p0 + bc);
        out[b0 + 1] = sigm(p1 + bc);
        out[b0 + 2] = sigm(p2 + bc);
        out[b0 + 3] = sigm(p3 + bc);
    }
}

extern "C" void kernel_launch(void* const* d_in, const int* in_sizes, int n_in,
                              void* d_out, int out_size) {
    (void)in_sizes; (void)n_in; (void)out_size;
    const float* x     = (const float*)d_in[0];
    const float* w_ih0 = (const float*)d_in[1];
    const float* w_hh0 = (const float*)d_in[2];
    const float* b_ih0 = (const float*)d_in[3];
    const float* b_hh0 = (const float*)d_in[4];
    const float* w_ih1 = (const float*)d_in[5];
    const float* w_hh1 = (const float*)d_in[6];
    const float* b_ih1 = (const float*)d_in[7];
    const float* b_hh1 = (const float*)d_in[8];
    const float* w_cls = (const float*)d_in[9];
    const float* b_cls = (const float*)d_in[10];

    gx_gemm_kernel<<<P1_BLOCKS, P1_THREADS>>>(x, w_ih0);
    gru_recurrent_kernel<<<NBLK2, NTHR2>>>(
        w_hh0, b_ih0, b_hh0, w_ih1, w_hh1, b_ih1, b_hh1,
        w_cls, b_cls, (float*)d_out);
}